// round 4
// baseline (speedup 1.0000x reference)
#include <cuda_runtime.h>
#include <stdint.h>

// Haar DWT level-1 on x: (B=32, L=4096, F=512) fp32.
// out[b, p, f]      = (x[b,2p,f] + x[b,2p+1,f]) / sqrt2   (p in [0,2048))
// out[b, 2048+p, f] = (x[b,2p,f] - x[b,2p+1,f]) / sqrt2
//
// Persistent grid-stride version: one wave of 148x8 CTAs, each looping over
// work items. Per iteration: two pairs at distant p, 4 independent coalesced
// LDG.128 (lane = f4, stride-1), plain loads, evict-first (.cs) stores.

#define B 32
#define L 4096
#define F 512
#define HALF_L (L / 2)
#define F4 (F / 4)                        // 128 float4 per row
#define PQ (HALF_L / 2)                   // 1024 pair-pairs
#define TOTAL_T (B * PQ * F4)             // 4,194,304 work items

#define NUM_SMS 148
#define CTAS_PER_SM 8
#define NBLOCKS (NUM_SMS * CTAS_PER_SM)   // 1184
#define NTHREADS 256

__global__ __launch_bounds__(NTHREADS) void haar_dwt_kernel(
    const float4* __restrict__ x, float4* __restrict__ out)
{
    const float s = 0.70710678118654752440f;
    const long row  = (long)F4;
    const long dOff = (long)HALF_L * F4;
    const int stride = NBLOCKS * NTHREADS;

    for (int t = blockIdx.x * NTHREADS + threadIdx.x; t < TOTAL_T; t += stride)
    {
        int f4 = t & (F4 - 1);            // lane-contiguous
        int p  = (t >> 7) & (PQ - 1);     // 0..1023
        int b  = t >> 17;                 // 0..31

        long base_b = (long)b * (L * F4);
        long in0 = base_b + (long)(2 * p) * row + f4;
        long in1 = base_b + (long)(2 * (p + PQ)) * row + f4;

        // 4 independent coalesced loads batched up front
        float4 a0 = x[in0];
        float4 a1 = x[in0 + row];
        float4 b0 = x[in1];
        float4 b1 = x[in1 + row];

        float4 ca0, cd0, ca1, cd1;
        ca0.x = (a0.x + a1.x) * s;  cd0.x = (a0.x - a1.x) * s;
        ca0.y = (a0.y + a1.y) * s;  cd0.y = (a0.y - a1.y) * s;
        ca0.z = (a0.z + a1.z) * s;  cd0.z = (a0.z - a1.z) * s;
        ca0.w = (a0.w + a1.w) * s;  cd0.w = (a0.w - a1.w) * s;
        ca1.x = (b0.x + b1.x) * s;  cd1.x = (b0.x - b1.x) * s;
        ca1.y = (b0.y + b1.y) * s;  cd1.y = (b0.y - b1.y) * s;
        ca1.z = (b0.z + b1.z) * s;  cd1.z = (b0.z - b1.z) * s;
        ca1.w = (b0.w + b1.w) * s;  cd1.w = (b0.w - b1.w) * s;

        long outA0 = base_b + (long)p * row + f4;
        long outA1 = base_b + (long)(p + PQ) * row + f4;

        __stcs(&out[outA0],        ca0);
        __stcs(&out[outA0 + dOff], cd0);
        __stcs(&out[outA1],        ca1);
        __stcs(&out[outA1 + dOff], cd1);
    }
}

extern "C" void kernel_launch(void* const* d_in, const int* in_sizes, int n_in,
                              void* d_out, int out_size)
{
    const float4* x = (const float4*)d_in[0];
    float4* out = (float4*)d_out;

    haar_dwt_kernel<<<NBLOCKS, NTHREADS>>>(x, out);
}

// round 5
// speedup vs baseline: 1.1165x; 1.1165x over previous
#include <cuda_runtime.h>
#include <stdint.h>

// Haar DWT level-1 on x: (B=32, L=4096, F=512) fp32.
// out[b, p, f]      = (x[b,2p,f] + x[b,2p+1,f]) / sqrt2   (p in [0,2048))
// out[b, 2048+p, f] = (x[b,2p,f] - x[b,2p+1,f]) / sqrt2
//
// R3 layout (best): lane = f4 stride-1 coalesced, MLP=4 via two distant pairs.
// Single change vs R3: loads use __ldcs (read-once, evict-first) so L2
// capacity favors the store stream. Stores stay PLAIN (.cs stores proved
// -7% DRAM duty in R2/R4).

#define B 32
#define L 4096
#define F 512
#define HALF_L (L / 2)
#define F4 (F / 4)                        // 128 float4 per row
#define PQ (HALF_L / 2)                   // 1024 pair-indices per thread-group
#define TOTAL_T (B * PQ * F4)             // 4,194,304 threads

__global__ __launch_bounds__(256) void haar_dwt_kernel(
    const float4* __restrict__ x, float4* __restrict__ out)
{
    int t = blockIdx.x * blockDim.x + threadIdx.x;

    int f4 = t & (F4 - 1);                // 0..127 (lane-contiguous)
    int p  = (t >> 7) & (PQ - 1);         // 0..1023
    int b  = t >> 17;                     // 0..31

    long row = (long)F4;
    long base_b = (long)b * (L * F4);

    long in0 = base_b + (long)(2 * p) * row + f4;
    long in1 = base_b + (long)(2 * (p + PQ)) * row + f4;

    // 4 independent coalesced loads batched up front, evict-first (no reuse)
    float4 a0 = __ldcs(&x[in0]);
    float4 a1 = __ldcs(&x[in0 + row]);
    float4 b0 = __ldcs(&x[in1]);
    float4 b1 = __ldcs(&x[in1 + row]);

    const float s = 0.70710678118654752440f;
    float4 ca0, cd0, ca1, cd1;
    ca0.x = (a0.x + a1.x) * s;  cd0.x = (a0.x - a1.x) * s;
    ca0.y = (a0.y + a1.y) * s;  cd0.y = (a0.y - a1.y) * s;
    ca0.z = (a0.z + a1.z) * s;  cd0.z = (a0.z - a1.z) * s;
    ca0.w = (a0.w + a1.w) * s;  cd0.w = (a0.w - a1.w) * s;
    ca1.x = (b0.x + b1.x) * s;  cd1.x = (b0.x - b1.x) * s;
    ca1.y = (b0.y + b1.y) * s;  cd1.y = (b0.y - b1.y) * s;
    ca1.z = (b0.z + b1.z) * s;  cd1.z = (b0.z - b1.z) * s;
    ca1.w = (b0.w + b1.w) * s;  cd1.w = (b0.w - b1.w) * s;

    long outA0 = base_b + (long)p * row + f4;
    long outA1 = base_b + (long)(p + PQ) * row + f4;
    long dOff  = (long)HALF_L * row;

    out[outA0]        = ca0;
    out[outA0 + dOff] = cd0;
    out[outA1]        = ca1;
    out[outA1 + dOff] = cd1;
}

extern "C" void kernel_launch(void* const* d_in, const int* in_sizes, int n_in,
                              void* d_out, int out_size)
{
    const float4* x = (const float4*)d_in[0];
    float4* out = (float4*)d_out;

    int threads = 256;
    int blocks = TOTAL_T / threads;       // 16384
    haar_dwt_kernel<<<blocks, threads>>>(x, out);
}

// round 6
// speedup vs baseline: 1.1234x; 1.0062x over previous
#include <cuda_runtime.h>
#include <stdint.h>

// Haar DWT level-1 on x: (B=32, L=4096, F=512) fp32.
// out[b, p, f]      = (x[b,2p,f] + x[b,2p+1,f]) / sqrt2   (p in [0,2048))
// out[b, 2048+p, f] = (x[b,2p,f] - x[b,2p+1,f]) / sqrt2
//
// R3 layout, MLP=8: four pairs at distant p per thread, all 8 coalesced
// LDG.128 batched up front. Plain loads/stores (hints proven harmful).

#define B 32
#define L 4096
#define F 512
#define HALF_L (L / 2)
#define F4 (F / 4)                        // 128 float4 per row
#define PQ (HALF_L / 4)                   // 512 pair-quads
#define TOTAL_T (B * PQ * F4)             // 2,097,152 threads

__global__ __launch_bounds__(256) void haar_dwt_kernel(
    const float4* __restrict__ x, float4* __restrict__ out)
{
    int t = blockIdx.x * blockDim.x + threadIdx.x;

    int f4 = t & (F4 - 1);                // lane-contiguous
    int p  = (t >> 7) & (PQ - 1);         // 0..511
    int b  = t >> 16;                     // 0..31

    const long row  = (long)F4;
    const long dOff = (long)HALF_L * F4;
    long base_b = (long)b * (L * F4);

    long in0 = base_b + (long)(2 * p)            * row + f4;
    long in1 = base_b + (long)(2 * (p +     PQ)) * row + f4;
    long in2 = base_b + (long)(2 * (p + 2 * PQ)) * row + f4;
    long in3 = base_b + (long)(2 * (p + 3 * PQ)) * row + f4;

    // 8 independent coalesced loads batched up front
    float4 a0 = x[in0];
    float4 a1 = x[in0 + row];
    float4 b0 = x[in1];
    float4 b1 = x[in1 + row];
    float4 c0 = x[in2];
    float4 c1 = x[in2 + row];
    float4 d0 = x[in3];
    float4 d1 = x[in3 + row];

    const float s = 0.70710678118654752440f;
    float4 sA, dA, sB, dB, sC, dC, sD, dD;
    sA.x = (a0.x + a1.x) * s;  dA.x = (a0.x - a1.x) * s;
    sA.y = (a0.y + a1.y) * s;  dA.y = (a0.y - a1.y) * s;
    sA.z = (a0.z + a1.z) * s;  dA.z = (a0.z - a1.z) * s;
    sA.w = (a0.w + a1.w) * s;  dA.w = (a0.w - a1.w) * s;
    sB.x = (b0.x + b1.x) * s;  dB.x = (b0.x - b1.x) * s;
    sB.y = (b0.y + b1.y) * s;  dB.y = (b0.y - b1.y) * s;
    sB.z = (b0.z + b1.z) * s;  dB.z = (b0.z - b1.z) * s;
    sB.w = (b0.w + b1.w) * s;  dB.w = (b0.w - b1.w) * s;
    sC.x = (c0.x + c1.x) * s;  dC.x = (c0.x - c1.x) * s;
    sC.y = (c0.y + c1.y) * s;  dC.y = (c0.y - c1.y) * s;
    sC.z = (c0.z + c1.z) * s;  dC.z = (c0.z - c1.z) * s;
    sC.w = (c0.w + c1.w) * s;  dC.w = (c0.w - c1.w) * s;
    sD.x = (d0.x + d1.x) * s;  dD.x = (d0.x - d1.x) * s;
    sD.y = (d0.y + d1.y) * s;  dD.y = (d0.y - d1.y) * s;
    sD.z = (d0.z + d1.z) * s;  dD.z = (d0.z - d1.z) * s;
    sD.w = (d0.w + d1.w) * s;  dD.w = (d0.w - d1.w) * s;

    long oA = base_b + (long)p            * row + f4;
    long oB = base_b + (long)(p +     PQ) * row + f4;
    long oC = base_b + (long)(p + 2 * PQ) * row + f4;
    long oD = base_b + (long)(p + 3 * PQ) * row + f4;

    out[oA]        = sA;
    out[oB]        = sB;
    out[oC]        = sC;
    out[oD]        = sD;
    out[oA + dOff] = dA;
    out[oB + dOff] = dB;
    out[oC + dOff] = dC;
    out[oD + dOff] = dD;
}

extern "C" void kernel_launch(void* const* d_in, const int* in_sizes, int n_in,
                              void* d_out, int out_size)
{
    const float4* x = (const float4*)d_in[0];
    float4* out = (float4*)d_out;

    int threads = 256;
    int blocks = TOTAL_T / threads;       // 8192
    haar_dwt_kernel<<<blocks, threads>>>(x, out);
}